// round 1
// baseline (speedup 1.0000x reference)
#include <cuda_runtime.h>
#include <math.h>

#define NN   50000
#define EE   800000
#define DIMD 128
#define HH   8
#define CATD 512
#define HIDD 512

// ---------------- scratch (device globals; no allocations allowed) ----------
__device__ __align__(16) float g_cat[(size_t)NN * CATD];   // [h | msg | sum2 | msg3]
__device__ __align__(16) float g_f[(size_t)NN * HIDD];     // gelu(cat@w1.T+b1)
__device__ __align__(16) float g_suv[NN * 16];             // su[0..7], sv[8..15]
__device__ __align__(16) float g_ex[(size_t)EE * 8];       // exp(leakyrelu(score))
__device__ __align__(16) float g_den[NN * 8];              // softmax denominators
__device__ float g_indeg[NN];
__device__ float g_outdeg[NN];

__device__ __forceinline__ void red4(float* p, float4 v) {
    asm volatile("red.global.add.v4.f32 [%0], {%1,%2,%3,%4};"
                 :: "l"(p), "f"(v.x), "f"(v.y), "f"(v.z), "f"(v.w) : "memory");
}

// ---------------- generic tiled fp32 GEMM: C = A[M,K] @ B[N,K]^T + bias -----
template <bool GELU>
__global__ void gemm_bias(const float* __restrict__ A, int lda,
                          const float* __restrict__ B,           // [N,K] row-major
                          const float* __restrict__ bias,        // may be null
                          float* __restrict__ C, int ldc,
                          int M, int N, int K)
{
    __shared__ float As[16][68];
    __shared__ float Bs[16][68];
    const int t  = threadIdx.x;           // 256 threads
    const int tm = t >> 4, tn = t & 15;
    const int m0 = blockIdx.y * 64, n0 = blockIdx.x * 64;

    float acc[4][4];
#pragma unroll
    for (int i = 0; i < 4; i++)
#pragma unroll
        for (int j = 0; j < 4; j++) acc[i][j] = 0.f;

    const int lr = t >> 2;        // 0..63 (tile row)
    const int lc = (t & 3) * 4;   // 0,4,8,12 (k offset)

    for (int k0 = 0; k0 < K; k0 += 16) {
        float4 av = make_float4(0.f, 0.f, 0.f, 0.f);
        int arow = m0 + lr;
        if (arow < M) av = *(const float4*)&A[(size_t)arow * lda + k0 + lc];
        As[lc + 0][lr] = av.x; As[lc + 1][lr] = av.y;
        As[lc + 2][lr] = av.z; As[lc + 3][lr] = av.w;

        float4 bv = make_float4(0.f, 0.f, 0.f, 0.f);
        int brow = n0 + lr;
        if (brow < N) bv = *(const float4*)&B[(size_t)brow * K + k0 + lc];
        Bs[lc + 0][lr] = bv.x; Bs[lc + 1][lr] = bv.y;
        Bs[lc + 2][lr] = bv.z; Bs[lc + 3][lr] = bv.w;

        __syncthreads();
#pragma unroll
        for (int k = 0; k < 16; k++) {
            float4 a = *(const float4*)&As[k][tm * 4];
            float4 b = *(const float4*)&Bs[k][tn * 4];
            acc[0][0] += a.x * b.x; acc[0][1] += a.x * b.y; acc[0][2] += a.x * b.z; acc[0][3] += a.x * b.w;
            acc[1][0] += a.y * b.x; acc[1][1] += a.y * b.y; acc[1][2] += a.y * b.z; acc[1][3] += a.y * b.w;
            acc[2][0] += a.z * b.x; acc[2][1] += a.z * b.y; acc[2][2] += a.z * b.z; acc[2][3] += a.z * b.w;
            acc[3][0] += a.w * b.x; acc[3][1] += a.w * b.y; acc[3][2] += a.w * b.z; acc[3][3] += a.w * b.w;
        }
        __syncthreads();
    }

#pragma unroll
    for (int i = 0; i < 4; i++) {
        int m = m0 + tm * 4 + i;
        if (m >= M) continue;
#pragma unroll
        for (int j = 0; j < 4; j++) {
            int n = n0 + tn * 4 + j;
            if (n >= N) continue;
            float v = acc[i][j] + (bias ? bias[n] : 0.f);
            if (GELU) v = 0.5f * v * (1.f + erff(v * 0.70710678118654752f));
            C[(size_t)m * ldc + n] = v;
        }
    }
}

// ---------------- su/sv: [N,8] each; thread per (n, j) with j in 0..15 ------
__global__ void suv_kernel(const float* __restrict__ au_w,
                           const float* __restrict__ au_b,
                           const float* __restrict__ av_w)
{
    int idx = blockIdx.x * blockDim.x + threadIdx.x;
    if (idx >= NN * 16) return;
    int n = idx >> 4;
    int j = idx & 15;
    const float* w = (j < 8) ? &au_w[j * DIMD] : &av_w[(j - 8) * DIMD];
    const float* hrow = &g_cat[(size_t)n * CATD];
    float s = 0.f;
#pragma unroll
    for (int i = 0; i < DIMD; i += 4) {
        float4 hv = *(const float4*)&hrow[i];
        float4 wv = *(const float4*)&w[i];
        s += hv.x * wv.x + hv.y * wv.y + hv.z * wv.z + hv.w * wv.w;
    }
    if (j < 8) s += au_b[j];
    g_suv[idx] = s;
}

// ---------------- edge pass 1: exp(leakyrelu(su[src]+sv[dst])), denominators,
//                  degrees. One thread per edge. ----------------------------
__global__ void edge_score_kernel(const int* __restrict__ src,
                                  const int* __restrict__ dst)
{
    int e = blockIdx.x * blockDim.x + threadIdx.x;
    if (e >= EE) return;
    int s = src[e], d = dst[e];
    const float* su = &g_suv[s * 16];
    const float* sv = &g_suv[d * 16 + 8];
    float ex[8];
#pragma unroll
    for (int k = 0; k < 8; k++) {
        float v = su[k] + sv[k];
        v = (v > 0.f) ? v : 0.2f * v;     // LeakyReLU(0.2)
        ex[k] = expf(v);                  // softmax shift-invariant: skip max
    }
    *(float4*)&g_ex[(size_t)e * 8 + 0] = make_float4(ex[0], ex[1], ex[2], ex[3]);
    *(float4*)&g_ex[(size_t)e * 8 + 4] = make_float4(ex[4], ex[5], ex[6], ex[7]);
    red4(&g_den[d * 8 + 0], make_float4(ex[0], ex[1], ex[2], ex[3]));
    red4(&g_den[d * 8 + 4], make_float4(ex[4], ex[5], ex[6], ex[7]));
    atomicAdd(&g_indeg[d], 1.f);
    atomicAdd(&g_outdeg[s], 1.f);
}

// ---------------- edge pass 2: fused 3-way aggregation. Warp per edge. ------
// msg  += h[src,d] * p[e, d%8]      -> cat cols 128..255
// sum2 += h[src,d]                  -> cat cols 256..383 (scaled by 1/deg later)
// msg3 += h[src,d] * norm[e]        -> cat cols 384..511
__global__ void edge_msg_kernel(const int* __restrict__ src,
                                const int* __restrict__ dst)
{
    int gid  = blockIdx.x * blockDim.x + threadIdx.x;
    int e    = gid >> 5;
    int lane = gid & 31;
    if (e >= EE) return;
    int s = src[e], d = dst[e];

    float norm = rsqrtf(g_outdeg[s] * g_outdeg[d]);

    int d0 = lane * 4;          // feature offset 0..124
    int kb = d0 & 7;            // head base (0 or 4); 4 consecutive heads
    float4 exv  = *(const float4*)&g_ex[(size_t)e * 8 + kb];
    float4 denv = *(const float4*)&g_den[d * 8 + kb];
    float4 p = make_float4(exv.x / denv.x, exv.y / denv.y,
                           exv.z / denv.z, exv.w / denv.w);

    float4 h = *(const float4*)&g_cat[(size_t)s * CATD + d0];

    float* base = &g_cat[(size_t)d * CATD];
    red4(base + 128 + d0, make_float4(h.x * p.x, h.y * p.y, h.z * p.z, h.w * p.w));
    red4(base + 256 + d0, h);
    red4(base + 384 + d0, make_float4(h.x * norm, h.y * norm, h.z * norm, h.w * norm));
}

// ---------------- scale sum2 -> mean (msg2) --------------------------------
__global__ void mean_scale_kernel()
{
    int idx = blockIdx.x * blockDim.x + threadIdx.x;
    if (idx >= NN * DIMD) return;
    int n = idx >> 7;
    int dd = idx & 127;
    float inv = 1.f / fmaxf(g_indeg[n], 1.f);
    g_cat[(size_t)n * CATD + 256 + dd] *= inv;
}

// ---------------------------------------------------------------------------
extern "C" void kernel_launch(void* const* d_in, const int* in_sizes, int n_in,
                              void* d_out, int out_size)
{
    const float* x    = (const float*)d_in[0];
    const int*   src  = (const int*)d_in[1];
    const int*   dst  = (const int*)d_in[2];
    const float* fc_w = (const float*)d_in[3];
    const float* fc_b = (const float*)d_in[4];
    const float* au_w = (const float*)d_in[5];
    const float* au_b = (const float*)d_in[6];
    const float* av_w = (const float*)d_in[7];
    const float* w1   = (const float*)d_in[8];
    const float* b1   = (const float*)d_in[9];
    const float* w2   = (const float*)d_in[10];
    const float* b2   = (const float*)d_in[11];
    float* out = (float*)d_out;

    void *p_cat, *p_f, *p_den, *p_ind, *p_outd;
    cudaGetSymbolAddress(&p_cat,  g_cat);
    cudaGetSymbolAddress(&p_f,    g_f);
    cudaGetSymbolAddress(&p_den,  g_den);
    cudaGetSymbolAddress(&p_ind,  g_indeg);
    cudaGetSymbolAddress(&p_outd, g_outdeg);

    cudaMemsetAsync(p_cat,  0, sizeof(float) * (size_t)NN * CATD, 0);
    cudaMemsetAsync(p_den,  0, sizeof(float) * NN * 8, 0);
    cudaMemsetAsync(p_ind,  0, sizeof(float) * NN, 0);
    cudaMemsetAsync(p_outd, 0, sizeof(float) * NN, 0);

    float* cat = (float*)p_cat;
    float* f   = (float*)p_f;

    const int MB = (NN + 63) / 64;   // 782

    // h = x @ fc_w.T + fc_b  -> cat cols 0..127
    gemm_bias<false><<<dim3(DIMD / 64, MB), 256>>>(x, DIMD, fc_w, fc_b,
                                                   cat, CATD, NN, DIMD, DIMD);
    // su/sv
    suv_kernel<<<(NN * 16 + 255) / 256, 256>>>(au_w, au_b, av_w);
    // edge softmax numerators + denominators + degrees
    edge_score_kernel<<<(EE + 255) / 256, 256>>>(src, dst);
    // fused aggregation (warp per edge)
    edge_msg_kernel<<<((size_t)EE * 32 + 255) / 256, 256>>>(src, dst);
    // sum2 -> mean
    mean_scale_kernel<<<(NN * DIMD + 255) / 256, 256>>>();
    // f = gelu(cat @ w1.T + b1)
    gemm_bias<true><<<dim3(HIDD / 64, MB), 256>>>(cat, CATD, w1, b1,
                                                  f, HIDD, NN, HIDD, CATD);
    // out = f @ w2.T + b2
    gemm_bias<false><<<dim3(DIMD / 64, MB), 256>>>(f, HIDD, w2, b2,
                                                   out, DIMD, NN, DIMD, HIDD);
}

// round 3
// speedup vs baseline: 1.7352x; 1.7352x over previous
#include <cuda_runtime.h>
#include <cstdint>
#include <math.h>

#define NN   50000
#define EE   800000
#define DIMD 128
#define CATD 512
#define HIDD 512

// ---------------- scratch (device globals; no allocations allowed) ----------
__device__ __align__(16) float g_cat[(size_t)NN * CATD];   // [h | msg | sum2 | msg3]
__device__ __align__(16) float g_f[(size_t)NN * HIDD];     // gelu(cat@w1.T+b1)
__device__ __align__(16) float g_suv[NN * 16];             // su[0..7], sv[8..15]
__device__ __align__(16) float g_ex[(size_t)EE * 8];       // exp(leakyrelu(score))
__device__ __align__(16) float g_den[NN * 8];              // softmax denominators
__device__ float g_indeg[NN];
__device__ float g_outdeg[NN];

__device__ __forceinline__ void red4(float* p, float4 v) {
    asm volatile("red.global.add.v4.f32 [%0], {%1,%2,%3,%4};"
                 :: "l"(p), "f"(v.x), "f"(v.y), "f"(v.z), "f"(v.w) : "memory");
}

__device__ __forceinline__ uint32_t to_tf32(float x) {
    uint32_t r;
    asm("cvt.rna.tf32.f32 %0, %1;" : "=r"(r) : "f"(x));
    return r;
}

// ---------------- tf32 mma.sync GEMM: C = A[M,K] @ B[N,K]^T + bias ----------
// CTA tile 128(M) x 128(N), K-chunk 64. 8 warps: warp w -> (w>>2)*64 M rows,
// (w&3)*32 N cols; each warp = 4x4 grid of m16n8k8 MMAs.
#define KCH   64
#define LDS_P 68     // row stride in floats (64 + 4 pad): conflict-free frags

template <bool GELU>
__global__ __launch_bounds__(256, 1) void gemm_mma(
    const float* __restrict__ A, int lda,
    const float* __restrict__ B, int ldb,   // [N,K] row-major
    const float* __restrict__ bias,
    float* __restrict__ C, int ldc,
    int M, int K)
{
    extern __shared__ float smf[];
    float* sA = smf;                  // [128][LDS_P]
    float* sB = smf + 128 * LDS_P;    // [128][LDS_P]

    const int tid  = threadIdx.x;
    const int wid  = tid >> 5, lane = tid & 31;
    const int g    = lane >> 2;       // group id 0..7
    const int tg   = lane & 3;        // thread in group
    const int m0   = blockIdx.y * 128;
    const int n0   = blockIdx.x * 128;
    const int mw   = (wid >> 2) * 64; // warp M offset in tile
    const int nw   = (wid & 3) * 32;  // warp N offset in tile

    float c[4][4][4];
#pragma unroll
    for (int i = 0; i < 4; i++)
#pragma unroll
        for (int j = 0; j < 4; j++)
#pragma unroll
            for (int q = 0; q < 4; q++) c[i][j][q] = 0.f;

    for (int kc = 0; kc < K; kc += KCH) {
        // ---- stage A,B chunk as tf32 (rna) into padded SMEM ----
#pragma unroll
        for (int it = 0; it < 8; it++) {
            int q   = tid + it * 256;          // 0..2047
            int row = q >> 4;
            int kq  = (q & 15) << 2;
            float4 v = make_float4(0.f, 0.f, 0.f, 0.f);
            int m = m0 + row;
            if (m < M) v = *(const float4*)&A[(size_t)m * lda + kc + kq];
            uint4 t;
            t.x = to_tf32(v.x); t.y = to_tf32(v.y);
            t.z = to_tf32(v.z); t.w = to_tf32(v.w);
            *(uint4*)&sA[row * LDS_P + kq] = t;

            float4 w = *(const float4*)&B[(size_t)(n0 + row) * ldb + kc + kq];
            uint4 u;
            u.x = to_tf32(w.x); u.y = to_tf32(w.y);
            u.z = to_tf32(w.z); u.w = to_tf32(w.w);
            *(uint4*)&sB[row * LDS_P + kq] = u;
        }
        __syncthreads();

        const uint32_t* uA = (const uint32_t*)sA;
        const uint32_t* uB = (const uint32_t*)sB;
#pragma unroll
        for (int ks = 0; ks < KCH / 8; ks++) {
            uint32_t a[4][4], b[4][2];
#pragma unroll
            for (int i = 0; i < 4; i++) {
                int r  = (mw + i * 16 + g) * LDS_P + ks * 8 + tg;
                a[i][0] = uA[r];
                a[i][1] = uA[r + 8 * LDS_P];
                a[i][2] = uA[r + 4];
                a[i][3] = uA[r + 8 * LDS_P + 4];
            }
#pragma unroll
            for (int j = 0; j < 4; j++) {
                int r = (nw + j * 8 + g) * LDS_P + ks * 8 + tg;
                b[j][0] = uB[r];
                b[j][1] = uB[r + 4];
            }
#pragma unroll
            for (int i = 0; i < 4; i++)
#pragma unroll
                for (int j = 0; j < 4; j++) {
                    asm volatile(
                        "mma.sync.aligned.m16n8k8.row.col.f32.tf32.tf32.f32 "
                        "{%0,%1,%2,%3}, {%4,%5,%6,%7}, {%8,%9}, {%0,%1,%2,%3};"
                        : "+f"(c[i][j][0]), "+f"(c[i][j][1]),
                          "+f"(c[i][j][2]), "+f"(c[i][j][3])
                        : "r"(a[i][0]), "r"(a[i][1]), "r"(a[i][2]), "r"(a[i][3]),
                          "r"(b[j][0]), "r"(b[j][1]));
                }
        }
        __syncthreads();
    }

    // ---- epilogue: bias (+GELU), store ----
#pragma unroll
    for (int i = 0; i < 4; i++) {
        int r0 = m0 + mw + i * 16 + g;
        int r1 = r0 + 8;
#pragma unroll
        for (int j = 0; j < 4; j++) {
            int n = n0 + nw + j * 8 + tg * 2;
            float bx = bias[n], by = bias[n + 1];
            float v0 = c[i][j][0] + bx, v1 = c[i][j][1] + by;
            float v2 = c[i][j][2] + bx, v3 = c[i][j][3] + by;
            if (GELU) {
                v0 = 0.5f * v0 * (1.f + erff(v0 * 0.70710678118654752f));
                v1 = 0.5f * v1 * (1.f + erff(v1 * 0.70710678118654752f));
                v2 = 0.5f * v2 * (1.f + erff(v2 * 0.70710678118654752f));
                v3 = 0.5f * v3 * (1.f + erff(v3 * 0.70710678118654752f));
            }
            if (r0 < M) {
                C[(size_t)r0 * ldc + n]     = v0;
                C[(size_t)r0 * ldc + n + 1] = v1;
            }
            if (r1 < M) {
                C[(size_t)r1 * ldc + n]     = v2;
                C[(size_t)r1 * ldc + n + 1] = v3;
            }
        }
    }
}

// ---------------- su/sv: [N,8] each; thread per (n, j) with j in 0..15 ------
__global__ void suv_kernel(const float* __restrict__ au_w,
                           const float* __restrict__ au_b,
                           const float* __restrict__ av_w)
{
    int idx = blockIdx.x * blockDim.x + threadIdx.x;
    if (idx >= NN * 16) return;
    int n = idx >> 4;
    int j = idx & 15;
    const float* w = (j < 8) ? &au_w[j * DIMD] : &av_w[(j - 8) * DIMD];
    const float* hrow = &g_cat[(size_t)n * CATD];
    float s = 0.f;
#pragma unroll
    for (int i = 0; i < DIMD; i += 4) {
        float4 hv = *(const float4*)&hrow[i];
        float4 wv = *(const float4*)&w[i];
        s += hv.x * wv.x + hv.y * wv.y + hv.z * wv.z + hv.w * wv.w;
    }
    if (j < 8) s += au_b[j];
    g_suv[idx] = s;
}

// ---------------- edge pass 1: scores, denominators, degrees ----------------
__global__ void edge_score_kernel(const int* __restrict__ src,
                                  const int* __restrict__ dst)
{
    int e = blockIdx.x * blockDim.x + threadIdx.x;
    if (e >= EE) return;
    int s = src[e], d = dst[e];
    const float* su = &g_suv[s * 16];
    const float* sv = &g_suv[d * 16 + 8];
    float ex[8];
#pragma unroll
    for (int k = 0; k < 8; k++) {
        float v = su[k] + sv[k];
        v = (v > 0.f) ? v : 0.2f * v;     // LeakyReLU(0.2)
        ex[k] = expf(v);                  // softmax shift-invariant: skip max
    }
    *(float4*)&g_ex[(size_t)e * 8 + 0] = make_float4(ex[0], ex[1], ex[2], ex[3]);
    *(float4*)&g_ex[(size_t)e * 8 + 4] = make_float4(ex[4], ex[5], ex[6], ex[7]);
    red4(&g_den[d * 8 + 0], make_float4(ex[0], ex[1], ex[2], ex[3]));
    red4(&g_den[d * 8 + 4], make_float4(ex[4], ex[5], ex[6], ex[7]));
    atomicAdd(&g_indeg[d], 1.f);
    atomicAdd(&g_outdeg[s], 1.f);
}

// ---------------- edge pass 2: fused 3-way aggregation. Warp per edge. ------
__global__ void edge_msg_kernel(const int* __restrict__ src,
                                const int* __restrict__ dst)
{
    int gid  = blockIdx.x * blockDim.x + threadIdx.x;
    int e    = gid >> 5;
    int lane = gid & 31;
    if (e >= EE) return;
    int s = src[e], d = dst[e];

    float norm = rsqrtf(g_outdeg[s] * g_outdeg[d]);

    int d0 = lane * 4;          // feature offset 0..124
    int kb = d0 & 7;            // head base (0 or 4)
    float4 exv  = *(const float4*)&g_ex[(size_t)e * 8 + kb];
    float4 denv = *(const float4*)&g_den[d * 8 + kb];
    float4 p = make_float4(exv.x / denv.x, exv.y / denv.y,
                           exv.z / denv.z, exv.w / denv.w);

    float4 h = *(const float4*)&g_cat[(size_t)s * CATD + d0];

    float* base = &g_cat[(size_t)d * CATD];
    red4(base + 128 + d0, make_float4(h.x * p.x, h.y * p.y, h.z * p.z, h.w * p.w));
    red4(base + 256 + d0, h);
    red4(base + 384 + d0, make_float4(h.x * norm, h.y * norm, h.z * norm, h.w * norm));
}

// ---------------- scale sum2 -> mean (msg2) --------------------------------
__global__ void mean_scale_kernel()
{
    int idx = blockIdx.x * blockDim.x + threadIdx.x;
    if (idx >= NN * DIMD) return;
    int n = idx >> 7;
    int dd = idx & 127;
    float inv = 1.f / fmaxf(g_indeg[n], 1.f);
    g_cat[(size_t)n * CATD + 256 + dd] *= inv;
}

// ---------------------------------------------------------------------------
extern "C" void kernel_launch(void* const* d_in, const int* in_sizes, int n_in,
                              void* d_out, int out_size)
{
    const float* x    = (const float*)d_in[0];
    const int*   src  = (const int*)d_in[1];
    const int*   dst  = (const int*)d_in[2];
    const float* fc_w = (const float*)d_in[3];
    const float* fc_b = (const float*)d_in[4];
    const float* au_w = (const float*)d_in[5];
    const float* au_b = (const float*)d_in[6];
    const float* av_w = (const float*)d_in[7];
    const float* w1   = (const float*)d_in[8];
    const float* b1   = (const float*)d_in[9];
    const float* w2   = (const float*)d_in[10];
    const float* b2   = (const float*)d_in[11];
    float* out = (float*)d_out;

    void *p_cat, *p_f, *p_den, *p_ind, *p_outd;
    cudaGetSymbolAddress(&p_cat,  g_cat);
    cudaGetSymbolAddress(&p_f,    g_f);
    cudaGetSymbolAddress(&p_den,  g_den);
    cudaGetSymbolAddress(&p_ind,  g_indeg);
    cudaGetSymbolAddress(&p_outd, g_outdeg);

    cudaMemsetAsync(p_cat,  0, sizeof(float) * (size_t)NN * CATD, 0);
    cudaMemsetAsync(p_den,  0, sizeof(float) * NN * 8, 0);
    cudaMemsetAsync(p_ind,  0, sizeof(float) * NN, 0);
    cudaMemsetAsync(p_outd, 0, sizeof(float) * NN, 0);

    float* cat = (float*)p_cat;
    float* f   = (float*)p_f;

    const int smbytes = 2 * 128 * LDS_P * 4;   // 69632
    cudaFuncSetAttribute(gemm_mma<false>, cudaFuncAttributeMaxDynamicSharedMemorySize, smbytes);
    cudaFuncSetAttribute(gemm_mma<true>,  cudaFuncAttributeMaxDynamicSharedMemorySize, smbytes);

    const int MB = (NN + 127) / 128;   // 391

    // h = x @ fc_w.T + fc_b  -> cat cols 0..127
    gemm_mma<false><<<dim3(1, MB), 256, smbytes>>>(x, DIMD, fc_w, DIMD, fc_b,
                                                   cat, CATD, NN, DIMD);
    // su/sv
    suv_kernel<<<(NN * 16 + 255) / 256, 256>>>(au_w, au_b, av_w);
    // edge softmax numerators + denominators + degrees
    edge_score_kernel<<<(EE + 255) / 256, 256>>>(src, dst);
    // fused aggregation (warp per edge)
    edge_msg_kernel<<<((size_t)EE * 32 + 255) / 256, 256>>>(src, dst);
    // sum2 -> mean
    mean_scale_kernel<<<(NN * DIMD + 255) / 256, 256>>>();
    // f = gelu(cat @ w1.T + b1)
    gemm_mma<true><<<dim3(HIDD / 128, MB), 256, smbytes>>>(cat, CATD, w1, CATD, b1,
                                                           f, HIDD, NN, CATD);
    // out = f @ w2.T + b2
    gemm_mma<false><<<dim3(DIMD / 128, MB), 256, smbytes>>>(f, HIDD, w2, HIDD, b2,
                                                            out, DIMD, NN, HIDD);
}

// round 4
// speedup vs baseline: 2.0322x; 1.1712x over previous
#include <cuda_runtime.h>
#include <cstdint>
#include <math.h>

#define NN   50000
#define EE   800000
#define DIMD 128
#define CATD 512
#define HIDD 512

// ---------------- scratch (device globals; no allocations allowed) ----------
__device__ __align__(16) float g_cat[(size_t)NN * CATD];   // [h | msg | msg2 | msg3]
__device__ __align__(16) float g_f[(size_t)NN * HIDD];     // gelu(cat@w1.T+b1)
__device__ __align__(16) float g_suv[NN * 16];             // su[0..7], sv[8..15]
__device__ __align__(16) float g_ex[(size_t)EE * 8];       // exp scores, SLOT order
__device__ float g_norm[EE];                               // sym-norm, SLOT order
__device__ int   g_din[NN];
__device__ int   g_dout[NN];
__device__ int   g_rowstart[NN + 1];
__device__ int   g_cursor[NN];
__device__ int   g_ssrc[EE];     // src node per slot
__device__ int   g_slotof[EE];   // edge -> slot

__device__ __forceinline__ uint32_t to_tf32(float x) {
    uint32_t r;
    asm("cvt.rna.tf32.f32 %0, %1;" : "=r"(r) : "f"(x));
    return r;
}

// ---------------- tf32 mma.sync GEMM: C = A[M,K] @ B[N,K]^T + bias ----------
#define KCH   64
#define LDS_P 68

template <bool GELU>
__global__ __launch_bounds__(256, 1) void gemm_mma(
    const float* __restrict__ A, int lda,
    const float* __restrict__ B, int ldb,
    const float* __restrict__ bias,
    float* __restrict__ C, int ldc,
    int M, int K)
{
    extern __shared__ float smf[];
    float* sA = smf;
    float* sB = smf + 128 * LDS_P;

    const int tid  = threadIdx.x;
    const int wid  = tid >> 5, lane = tid & 31;
    const int g    = lane >> 2;
    const int tg   = lane & 3;
    const int m0   = blockIdx.y * 128;
    const int n0   = blockIdx.x * 128;
    const int mw   = (wid >> 2) * 64;
    const int nw   = (wid & 3) * 32;

    float c[4][4][4];
#pragma unroll
    for (int i = 0; i < 4; i++)
#pragma unroll
        for (int j = 0; j < 4; j++)
#pragma unroll
            for (int q = 0; q < 4; q++) c[i][j][q] = 0.f;

    for (int kc = 0; kc < K; kc += KCH) {
#pragma unroll
        for (int it = 0; it < 8; it++) {
            int q   = tid + it * 256;
            int row = q >> 4;
            int kq  = (q & 15) << 2;
            float4 v = make_float4(0.f, 0.f, 0.f, 0.f);
            int m = m0 + row;
            if (m < M) v = *(const float4*)&A[(size_t)m * lda + kc + kq];
            uint4 t;
            t.x = to_tf32(v.x); t.y = to_tf32(v.y);
            t.z = to_tf32(v.z); t.w = to_tf32(v.w);
            *(uint4*)&sA[row * LDS_P + kq] = t;

            float4 w = *(const float4*)&B[(size_t)(n0 + row) * ldb + kc + kq];
            uint4 u;
            u.x = to_tf32(w.x); u.y = to_tf32(w.y);
            u.z = to_tf32(w.z); u.w = to_tf32(w.w);
            *(uint4*)&sB[row * LDS_P + kq] = u;
        }
        __syncthreads();

        const uint32_t* uA = (const uint32_t*)sA;
        const uint32_t* uB = (const uint32_t*)sB;
#pragma unroll
        for (int ks = 0; ks < KCH / 8; ks++) {
            uint32_t a[4][4], b[4][2];
#pragma unroll
            for (int i = 0; i < 4; i++) {
                int r  = (mw + i * 16 + g) * LDS_P + ks * 8 + tg;
                a[i][0] = uA[r];
                a[i][1] = uA[r + 8 * LDS_P];
                a[i][2] = uA[r + 4];
                a[i][3] = uA[r + 8 * LDS_P + 4];
            }
#pragma unroll
            for (int j = 0; j < 4; j++) {
                int r = (nw + j * 8 + g) * LDS_P + ks * 8 + tg;
                b[j][0] = uB[r];
                b[j][1] = uB[r + 4];
            }
#pragma unroll
            for (int i = 0; i < 4; i++)
#pragma unroll
                for (int j = 0; j < 4; j++) {
                    asm volatile(
                        "mma.sync.aligned.m16n8k8.row.col.f32.tf32.tf32.f32 "
                        "{%0,%1,%2,%3}, {%4,%5,%6,%7}, {%8,%9}, {%0,%1,%2,%3};"
                        : "+f"(c[i][j][0]), "+f"(c[i][j][1]),
                          "+f"(c[i][j][2]), "+f"(c[i][j][3])
                        : "r"(a[i][0]), "r"(a[i][1]), "r"(a[i][2]), "r"(a[i][3]),
                          "r"(b[j][0]), "r"(b[j][1]));
                }
        }
        __syncthreads();
    }

#pragma unroll
    for (int i = 0; i < 4; i++) {
        int r0 = m0 + mw + i * 16 + g;
        int r1 = r0 + 8;
#pragma unroll
        for (int j = 0; j < 4; j++) {
            int n = n0 + nw + j * 8 + tg * 2;
            float bx = bias[n], by = bias[n + 1];
            float v0 = c[i][j][0] + bx, v1 = c[i][j][1] + by;
            float v2 = c[i][j][2] + bx, v3 = c[i][j][3] + by;
            if (GELU) {
                v0 = 0.5f * v0 * (1.f + erff(v0 * 0.70710678118654752f));
                v1 = 0.5f * v1 * (1.f + erff(v1 * 0.70710678118654752f));
                v2 = 0.5f * v2 * (1.f + erff(v2 * 0.70710678118654752f));
                v3 = 0.5f * v3 * (1.f + erff(v3 * 0.70710678118654752f));
            }
            if (r0 < M) {
                C[(size_t)r0 * ldc + n]     = v0;
                C[(size_t)r0 * ldc + n + 1] = v1;
            }
            if (r1 < M) {
                C[(size_t)r1 * ldc + n]     = v2;
                C[(size_t)r1 * ldc + n + 1] = v3;
            }
        }
    }
}

// ---------------- su/sv ----------------------------------------------------
__global__ void suv_kernel(const float* __restrict__ au_w,
                           const float* __restrict__ au_b,
                           const float* __restrict__ av_w)
{
    int idx = blockIdx.x * blockDim.x + threadIdx.x;
    if (idx >= NN * 16) return;
    int n = idx >> 4;
    int j = idx & 15;
    const float* w = (j < 8) ? &au_w[j * DIMD] : &av_w[(j - 8) * DIMD];
    const float* hrow = &g_cat[(size_t)n * CATD];
    float s = 0.f;
#pragma unroll
    for (int i = 0; i < DIMD; i += 4) {
        float4 hv = *(const float4*)&hrow[i];
        float4 wv = *(const float4*)&w[i];
        s += hv.x * wv.x + hv.y * wv.y + hv.z * wv.z + hv.w * wv.w;
    }
    if (j < 8) s += au_b[j];
    g_suv[idx] = s;
}

// ---------------- CSR build: degree histogram -------------------------------
__global__ void deg_kernel(const int* __restrict__ src,
                           const int* __restrict__ dst)
{
    int e = blockIdx.x * blockDim.x + threadIdx.x;
    if (e >= EE) return;
    atomicAdd(&g_din[dst[e]], 1);
    atomicAdd(&g_dout[src[e]], 1);
}

// ---------------- exclusive scan of g_din -> g_rowstart (single block) ------
__global__ __launch_bounds__(1024, 1) void scan_kernel()
{
    __shared__ int part[1024];
    const int t = threadIdx.x;
    const int PER = (NN + 1023) / 1024;   // 49
    const int base = t * PER;
    int s = 0;
    for (int i = 0; i < PER; i++) {
        int n = base + i;
        if (n < NN) s += g_din[n];
    }
    part[t] = s;
    __syncthreads();
    for (int off = 1; off < 1024; off <<= 1) {
        int v = (t >= off) ? part[t - off] : 0;
        __syncthreads();
        part[t] += v;
        __syncthreads();
    }
    int run = (t == 0) ? 0 : part[t - 1];
    for (int i = 0; i < PER; i++) {
        int n = base + i;
        if (n < NN) {
            g_rowstart[n] = run;
            run += g_din[n];
        }
    }
    if (t == 1023) g_rowstart[NN] = run;
}

// ---------------- scatter edges to dst-grouped slots ------------------------
__global__ void scatter_kernel(const int* __restrict__ src,
                               const int* __restrict__ dst)
{
    int e = blockIdx.x * blockDim.x + threadIdx.x;
    if (e >= EE) return;
    int d = dst[e];
    int pos  = atomicAdd(&g_cursor[d], 1);
    int slot = g_rowstart[d] + pos;
    g_ssrc[slot]  = src[e];
    g_slotof[e]   = slot;
}

// ---------------- edge scores: ex (slot order) + norm -----------------------
__global__ void edge_score_kernel(const int* __restrict__ src,
                                  const int* __restrict__ dst)
{
    int e = blockIdx.x * blockDim.x + threadIdx.x;
    if (e >= EE) return;
    int s = src[e], d = dst[e];
    int slot = g_slotof[e];
    const float* su = &g_suv[s * 16];
    const float* sv = &g_suv[d * 16 + 8];
    float ex[8];
#pragma unroll
    for (int k = 0; k < 8; k++) {
        float v = su[k] + sv[k];
        v = (v > 0.f) ? v : 0.2f * v;     // LeakyReLU(0.2)
        ex[k] = expf(v);                  // softmax shift-invariant: skip max
    }
    *(float4*)&g_ex[(size_t)slot * 8 + 0] = make_float4(ex[0], ex[1], ex[2], ex[3]);
    *(float4*)&g_ex[(size_t)slot * 8 + 4] = make_float4(ex[4], ex[5], ex[6], ex[7]);
    g_norm[slot] = rsqrtf((float)g_dout[s] * (float)g_dout[d]);
}

// ---------------- warp-per-dst fused aggregation (no atomics) ---------------
__global__ __launch_bounds__(256) void agg_kernel()
{
    int gw   = (blockIdx.x * blockDim.x + threadIdx.x) >> 5;
    int lane = threadIdx.x & 31;
    if (gw >= NN) return;
    const int d  = gw;
    const int r0 = g_rowstart[d];
    const int r1 = g_rowstart[d + 1];
    const int deg = r1 - r0;

    // pass 1: softmax denominators (8 heads)
    float den[8] = {0.f, 0.f, 0.f, 0.f, 0.f, 0.f, 0.f, 0.f};
    for (int i = r0 + lane; i < r1; i += 32) {
        float4 a = *(const float4*)&g_ex[(size_t)i * 8];
        float4 b = *(const float4*)&g_ex[(size_t)i * 8 + 4];
        den[0] += a.x; den[1] += a.y; den[2] += a.z; den[3] += a.w;
        den[4] += b.x; den[5] += b.y; den[6] += b.z; den[7] += b.w;
    }
#pragma unroll
    for (int k = 0; k < 8; k++)
#pragma unroll
        for (int off = 16; off; off >>= 1)
            den[k] += __shfl_xor_sync(0xFFFFFFFFu, den[k], off);

    const int d0 = lane * 4;
    const int kb = d0 & 7;
    float4 invden;
    invden.x = 1.f / den[kb + 0];
    invden.y = 1.f / den[kb + 1];
    invden.z = 1.f / den[kb + 2];
    invden.w = 1.f / den[kb + 3];

    // pass 2: accumulate msg / sum / msg3 in registers
    float4 am = make_float4(0.f, 0.f, 0.f, 0.f);
    float4 as = make_float4(0.f, 0.f, 0.f, 0.f);
    float4 a3 = make_float4(0.f, 0.f, 0.f, 0.f);
#pragma unroll 2
    for (int i = r0; i < r1; i++) {
        int   s   = g_ssrc[i];
        float nrm = g_norm[i];
        float4 ex = *(const float4*)&g_ex[(size_t)i * 8 + kb];
        float4 h  = *(const float4*)&g_cat[(size_t)s * CATD + d0];
        am.x += h.x * ex.x * invden.x;
        am.y += h.y * ex.y * invden.y;
        am.z += h.z * ex.z * invden.z;
        am.w += h.w * ex.w * invden.w;
        as.x += h.x; as.y += h.y; as.z += h.z; as.w += h.w;
        a3.x += h.x * nrm; a3.y += h.y * nrm;
        a3.z += h.z * nrm; a3.w += h.w * nrm;
    }

    float invd = 1.f / fmaxf((float)deg, 1.f);
    float* base = &g_cat[(size_t)d * CATD];
    *(float4*)(base + 128 + d0) = am;
    *(float4*)(base + 256 + d0) = make_float4(as.x * invd, as.y * invd,
                                              as.z * invd, as.w * invd);
    *(float4*)(base + 384 + d0) = a3;
}

// ---------------------------------------------------------------------------
extern "C" void kernel_launch(void* const* d_in, const int* in_sizes, int n_in,
                              void* d_out, int out_size)
{
    const float* x    = (const float*)d_in[0];
    const int*   src  = (const int*)d_in[1];
    const int*   dst  = (const int*)d_in[2];
    const float* fc_w = (const float*)d_in[3];
    const float* fc_b = (const float*)d_in[4];
    const float* au_w = (const float*)d_in[5];
    const float* au_b = (const float*)d_in[6];
    const float* av_w = (const float*)d_in[7];
    const float* w1   = (const float*)d_in[8];
    const float* b1   = (const float*)d_in[9];
    const float* w2   = (const float*)d_in[10];
    const float* b2   = (const float*)d_in[11];
    float* out = (float*)d_out;

    void *p_cat, *p_f, *p_din, *p_dout, *p_cur;
    cudaGetSymbolAddress(&p_cat,  g_cat);
    cudaGetSymbolAddress(&p_f,    g_f);
    cudaGetSymbolAddress(&p_din,  g_din);
    cudaGetSymbolAddress(&p_dout, g_dout);
    cudaGetSymbolAddress(&p_cur,  g_cursor);

    cudaMemsetAsync(p_din,  0, sizeof(int) * NN, 0);
    cudaMemsetAsync(p_dout, 0, sizeof(int) * NN, 0);
    cudaMemsetAsync(p_cur,  0, sizeof(int) * NN, 0);

    float* cat = (float*)p_cat;
    float* f   = (float*)p_f;

    const int smbytes = 2 * 128 * LDS_P * 4;   // 69632
    cudaFuncSetAttribute(gemm_mma<false>, cudaFuncAttributeMaxDynamicSharedMemorySize, smbytes);
    cudaFuncSetAttribute(gemm_mma<true>,  cudaFuncAttributeMaxDynamicSharedMemorySize, smbytes);

    const int MB = (NN + 127) / 128;   // 391

    // h = x @ fc_w.T + fc_b  -> cat cols 0..127
    gemm_mma<false><<<dim3(1, MB), 256, smbytes>>>(x, DIMD, fc_w, DIMD, fc_b,
                                                   cat, CATD, NN, DIMD);
    // CSR build (independent of h)
    deg_kernel<<<(EE + 255) / 256, 256>>>(src, dst);
    scan_kernel<<<1, 1024>>>();
    scatter_kernel<<<(EE + 255) / 256, 256>>>(src, dst);
    // su/sv
    suv_kernel<<<(NN * 16 + 255) / 256, 256>>>(au_w, au_b, av_w);
    // edge scores + norm (slot order)
    edge_score_kernel<<<(EE + 255) / 256, 256>>>(src, dst);
    // warp-per-dst aggregation, no atomics
    agg_kernel<<<(NN * 32 + 255) / 256, 256>>>();
    // f = gelu(cat @ w1.T + b1)
    gemm_mma<true><<<dim3(HIDD / 128, MB), 256, smbytes>>>(cat, CATD, w1, CATD, b1,
                                                           f, HIDD, NN, CATD);
    // out = f @ w2.T + b2
    gemm_mma<false><<<dim3(DIMD / 128, MB), 256, smbytes>>>(f, HIDD, w2, HIDD, b2,
                                                            out, DIMD, NN, HIDD);
}

// round 7
// speedup vs baseline: 2.0848x; 1.0258x over previous
#include <cuda_runtime.h>
#include <cstdint>
#include <math.h>

#define NN   50000
#define EE   800000
#define DIMD 128
#define CATD 512
#define HIDD 512

// ---------------- scratch (device globals; no allocations allowed) ----------
__device__ __align__(16) float g_cat[(size_t)NN * CATD];   // [h | msg | msg2 | msg3]
__device__ __align__(16) float g_f[(size_t)NN * HIDD];     // gelu(cat@w1.T+b1)
__device__ __align__(16) float g_suv[NN * 16];             // su[0..7], sv[8..15]
__device__ __align__(16) float g_ex[(size_t)EE * 8];       // exp scores, SLOT order
__device__ float g_norm[EE];                               // sym-norm, SLOT order
__device__ int   g_din[NN];
__device__ int   g_dout[NN];
__device__ int   g_rowstart[NN + 1];
__device__ int   g_cursor[NN];
__device__ int   g_ssrc[EE];     // src node per slot
__device__ int   g_slotof[EE];   // edge -> slot

__device__ __forceinline__ uint32_t to_tf32(float x) {
    uint32_t r;
    asm("cvt.rna.tf32.f32 %0, %1;" : "=r"(r) : "f"(x));
    return r;
}

__device__ __forceinline__ void cpa16(uint32_t dst, const void* src, int pbytes) {
    asm volatile("cp.async.cg.shared.global [%0], [%1], 16, %2;"
                 :: "r"(dst), "l"(src), "r"(pbytes));
}
__device__ __forceinline__ void cpa_commit() {
    asm volatile("cp.async.commit_group;");
}
template <int NG>
__device__ __forceinline__ void cpa_wait() {
    asm volatile("cp.async.wait_group %0;" :: "n"(NG));
}

// ---------------- tf32 mma.sync GEMM: C = A[M,K] @ B[N,K]^T + bias ----------
// CTA tile 128(M) x NT(N), K-chunk 64, double-buffered via cp.async.
// NT=128: warp 64x32 (4x4 MMA grid). NT=256: warp 64x64 (4x8 MMA grid).
#define KCH   64
#define LDS_P 68

template <int NT, bool GELU>
__global__ __launch_bounds__(256, 1) void gemm_mma(
    const float* __restrict__ A, int lda,
    const float* __restrict__ B, int ldb,
    const float* __restrict__ bias,
    float* __restrict__ C, int ldc,
    int M, int K)
{
    constexpr int ASZ = 128 * LDS_P;         // floats
    constexpr int BSZ = NT  * LDS_P;
    constexpr int NJ  = NT / 64;             // b-frag count = NJ*2
    extern __shared__ float smf[];

    const int tid  = threadIdx.x;
    const int wid  = tid >> 5, lane = tid & 31;
    const int g    = lane >> 2;
    const int tg   = lane & 3;
    const int m0   = blockIdx.y * 128;
    const int n0   = blockIdx.x * NT;
    const int mw   = (wid >> 2) * 64;
    const int nw   = (wid & 3) * (NT / 4);

    float c[4][NJ * 2][4];
#pragma unroll
    for (int i = 0; i < 4; i++)
#pragma unroll
        for (int j = 0; j < NJ * 2; j++)
#pragma unroll
            for (int q = 0; q < 4; q++) c[i][j][q] = 0.f;

    const int KC = K / KCH;

    // ---- async stage of chunk c into buffer buf ----
    auto stage = [&](int c, int buf) {
        const int kc = c * KCH;
        float* sA = smf + buf * (ASZ + BSZ);
        float* sB = sA + ASZ;
        uint32_t sAu = (uint32_t)__cvta_generic_to_shared(sA);
        uint32_t sBu = (uint32_t)__cvta_generic_to_shared(sB);
#pragma unroll
        for (int it = 0; it < 8; it++) {             // 128 rows x 16 float4
            int q   = tid + it * 256;
            int row = q >> 4;
            int kq  = (q & 15) << 2;
            int m   = m0 + row;
            int ok  = (m < M) ? 16 : 0;
            const float* srcp = &A[(size_t)(ok ? m : 0) * lda + kc + kq];
            cpa16(sAu + (row * LDS_P + kq) * 4, srcp, ok);
        }
#pragma unroll
        for (int it = 0; it < NT / 16; it++) {       // NT rows x 16 float4
            int q   = tid + it * 256;
            int row = q >> 4;
            int kq  = (q & 15) << 2;
            cpa16(sBu + (row * LDS_P + kq) * 4,
                  &B[(size_t)(n0 + row) * ldb + kc + kq], 16);
        }
        cpa_commit();
    };

    stage(0, 0);

    for (int cch = 0; cch < KC; cch++) {
        if (cch + 1 < KC) {
            stage(cch + 1, (cch + 1) & 1);
            cpa_wait<1>();
        } else {
            cpa_wait<0>();
        }
        __syncthreads();

        const float* sA = smf + (cch & 1) * (ASZ + BSZ);
        const float* sB = sA + ASZ;
        const uint32_t* uA = (const uint32_t*)sA;
        const uint32_t* uB = (const uint32_t*)sB;
#pragma unroll
        for (int ks = 0; ks < KCH / 8; ks++) {
            uint32_t a[4][4], b[NJ * 2][2];
#pragma unroll
            for (int i = 0; i < 4; i++) {
                int r  = (mw + i * 16 + g) * LDS_P + ks * 8 + tg;
                a[i][0] = to_tf32(__uint_as_float(uA[r]));
                a[i][1] = to_tf32(__uint_as_float(uA[r + 8 * LDS_P]));
                a[i][2] = to_tf32(__uint_as_float(uA[r + 4]));
                a[i][3] = to_tf32(__uint_as_float(uA[r + 8 * LDS_P + 4]));
            }
#pragma unroll
            for (int j = 0; j < NJ * 2; j++) {
                int r = (nw + j * 8 + g) * LDS_P + ks * 8 + tg;
                b[j][0] = to_tf32(__uint_as_float(uB[r]));
                b[j][1] = to_tf32(__uint_as_float(uB[r + 4]));
            }
#pragma unroll
            for (int i = 0; i < 4; i++)
#pragma unroll
                for (int j = 0; j < NJ * 2; j++) {
                    asm volatile(
                        "mma.sync.aligned.m16n8k8.row.col.f32.tf32.tf32.f32 "
                        "{%0,%1,%2,%3}, {%4,%5,%6,%7}, {%8,%9}, {%0,%1,%2,%3};"
                        : "+f"(c[i][j][0]), "+f"(c[i][j][1]),
                          "+f"(c[i][j][2]), "+f"(c[i][j][3])
                        : "r"(a[i][0]), "r"(a[i][1]), "r"(a[i][2]), "r"(a[i][3]),
                          "r"(b[j][0]), "r"(b[j][1]));
                }
        }
        __syncthreads();
    }

    // ---- epilogue: bias (+GELU), store ----
#pragma unroll
    for (int i = 0; i < 4; i++) {
        int r0 = m0 + mw + i * 16 + g;
        int r1 = r0 + 8;
#pragma unroll
        for (int j = 0; j < NJ * 2; j++) {
            int n = n0 + nw + j * 8 + tg * 2;
            float bx = bias[n], by = bias[n + 1];
            float v0 = c[i][j][0] + bx, v1 = c[i][j][1] + by;
            float v2 = c[i][j][2] + bx, v3 = c[i][j][3] + by;
            if (GELU) {
                v0 = 0.5f * v0 * (1.f + erff(v0 * 0.70710678118654752f));
                v1 = 0.5f * v1 * (1.f + erff(v1 * 0.70710678118654752f));
                v2 = 0.5f * v2 * (1.f + erff(v2 * 0.70710678118654752f));
                v3 = 0.5f * v3 * (1.f + erff(v3 * 0.70710678118654752f));
            }
            if (r0 < M) {
                C[(size_t)r0 * ldc + n]     = v0;
                C[(size_t)r0 * ldc + n + 1] = v1;
            }
            if (r1 < M) {
                C[(size_t)r1 * ldc + n]     = v2;
                C[(size_t)r1 * ldc + n + 1] = v3;
            }
        }
    }
}

// ---------------- su/sv ----------------------------------------------------
__global__ void suv_kernel(const float* __restrict__ au_w,
                           const float* __restrict__ au_b,
                           const float* __restrict__ av_w)
{
    int idx = blockIdx.x * blockDim.x + threadIdx.x;
    if (idx >= NN * 16) return;
    int n = idx >> 4;
    int j = idx & 15;
    const float* w = (j < 8) ? &au_w[j * DIMD] : &av_w[(j - 8) * DIMD];
    const float* hrow = &g_cat[(size_t)n * CATD];
    float s = 0.f;
#pragma unroll
    for (int i = 0; i < DIMD; i += 4) {
        float4 hv = *(const float4*)&hrow[i];
        float4 wv = *(const float4*)&w[i];
        s += hv.x * wv.x + hv.y * wv.y + hv.z * wv.z + hv.w * wv.w;
    }
    if (j < 8) s += au_b[j];
    g_suv[idx] = s;
}

// ---------------- CSR build: degree histogram -------------------------------
__global__ void deg_kernel(const int* __restrict__ src,
                           const int* __restrict__ dst)
{
    int e = blockIdx.x * blockDim.x + threadIdx.x;
    if (e >= EE) return;
    atomicAdd(&g_din[dst[e]], 1);
    atomicAdd(&g_dout[src[e]], 1);
}

// ---------------- exclusive scan of g_din -> g_rowstart (single block) ------
__global__ __launch_bounds__(1024, 1) void scan_kernel()
{
    __shared__ int part[1024];
    const int t = threadIdx.x;
    const int PER = (NN + 1023) / 1024;   // 49
    const int base = t * PER;
    int s = 0;
    for (int i = 0; i < PER; i++) {
        int n = base + i;
        if (n < NN) s += g_din[n];
    }
    part[t] = s;
    __syncthreads();
    for (int off = 1; off < 1024; off <<= 1) {
        int v = (t >= off) ? part[t - off] : 0;
        __syncthreads();
        part[t] += v;
        __syncthreads();
    }
    int run = (t == 0) ? 0 : part[t - 1];
    for (int i = 0; i < PER; i++) {
        int n = base + i;
        if (n < NN) {
            g_rowstart[n] = run;
            run += g_din[n];
        }
    }
    if (t == 1023) g_rowstart[NN] = run;
}

// ---------------- scatter edges to dst-grouped slots ------------------------
__global__ void scatter_kernel(const int* __restrict__ src,
                               const int* __restrict__ dst)
{
    int e = blockIdx.x * blockDim.x + threadIdx.x;
    if (e >= EE) return;
    int d = dst[e];
    int pos  = atomicAdd(&g_cursor[d], 1);
    int slot = g_rowstart[d] + pos;
    g_ssrc[slot]  = src[e];
    g_slotof[e]   = slot;
}

// ---------------- edge scores: ex (slot order) + norm -----------------------
__global__ void edge_score_kernel(const int* __restrict__ src,
                                  const int* __restrict__ dst)
{
    int e = blockIdx.x * blockDim.x + threadIdx.x;
    if (e >= EE) return;
    int s = src[e], d = dst[e];
    int slot = g_slotof[e];
    const float* su = &g_suv[s * 16];
    const float* sv = &g_suv[d * 16 + 8];
    float ex[8];
#pragma unroll
    for (int k = 0; k < 8; k++) {
        float v = su[k] + sv[k];
        v = (v > 0.f) ? v : 0.2f * v;     // LeakyReLU(0.2)
        ex[k] = __expf(v);                // fast exp; softmax shift-invariant
    }
    *(float4*)&g_ex[(size_t)slot * 8 + 0] = make_float4(ex[0], ex[1], ex[2], ex[3]);
    *(float4*)&g_ex[(size_t)slot * 8 + 4] = make_float4(ex[4], ex[5], ex[6], ex[7]);
    g_norm[slot] = rsqrtf((float)g_dout[s] * (float)g_dout[d]);
}

// ---------------- warp-per-dst fused aggregation (no atomics) ---------------
__global__ __launch_bounds__(256) void agg_kernel()
{
    int gw   = (blockIdx.x * blockDim.x + threadIdx.x) >> 5;
    int lane = threadIdx.x & 31;
    if (gw >= NN) return;
    const int d  = gw;
    const int r0 = g_rowstart[d];
    const int r1 = g_rowstart[d + 1];
    const int deg = r1 - r0;

    // pass 1: softmax denominators (8 heads)
    float den[8] = {0.f, 0.f, 0.f, 0.f, 0.f, 0.f, 0.f, 0.f};
    for (int i = r0 + lane; i < r1; i += 32) {
        float4 a = *(const float4*)&g_ex[(size_t)i * 8];
        float4 b = *(const float4*)&g_ex[(size_t)i * 8 + 4];
        den[0] += a.x; den[1] += a.y; den[2] += a.z; den[3] += a.w;
        den[4] += b.x; den[5] += b.y; den[6] += b.z; den[7] += b.w;
    }
#pragma unroll
    for (int k = 0; k < 8; k++)
#pragma unroll
        for (int off = 16; off; off >>= 1)
            den[k] += __shfl_xor_sync(0xFFFFFFFFu, den[k], off);

    const int d0 = lane * 4;
    const int kb = d0 & 7;
    float4 invden;
    invden.x = 1.f / den[kb + 0];
    invden.y = 1.f / den[kb + 1];
    invden.z = 1.f / den[kb + 2];
    invden.w = 1.f / den[kb + 3];

    // pass 2: accumulate msg / sum / msg3 in registers
    float4 am = make_float4(0.f, 0.f, 0.f, 0.f);
    float4 as = make_float4(0.f, 0.f, 0.f, 0.f);
    float4 a3 = make_float4(0.f, 0.f, 0.f, 0.f);
#pragma unroll 2
    for (int i = r0; i < r1; i++) {
        int   s   = g_ssrc[i];
        float nrm = g_norm[i];
        float4 ex = *(const float4*)&g_ex[(size_t)i * 8 + kb];
        float4 h  = *(const float4*)&g_cat[(size_t)s * CATD + d0];
        am.x += h.x * ex.x * invden.x;
        am.y += h.y * ex.y * invden.y;
        am.z += h.z * ex.z * invden.z;
        am.w += h.w * ex.w * invden.w;
        as.x += h.x; as.y += h.y; as.z += h.z; as.w += h.w;
        a3.x += h.x * nrm; a3.y += h.y * nrm;
        a3.z += h.z * nrm; a3.w += h.w * nrm;
    }

    float invd = 1.f / fmaxf((float)deg, 1.f);
    float* base = &g_cat[(size_t)d * CATD];
    *(float4*)(base + 128 + d0) = am;
    *(float4*)(base + 256 + d0) = make_float4(as.x * invd, as.y * invd,
                                              as.z * invd, as.w * invd);
    *(float4*)(base + 384 + d0) = a3;
}

// ---------------------------------------------------------------------------
extern "C" void kernel_launch(void* const* d_in, const int* in_sizes, int n_in,
                              void* d_out, int out_size)
{
    const float* x    = (const float*)d_in[0];
    const int*   src  = (const int*)d_in[1];
    const int*   dst  = (const int*)d_in[2];
    const float* fc_w = (const float*)d_in[3];
    const float* fc_b = (const float*)d_in[4];
    const float* au_w = (const float*)d_in[5];
    const float* au_b = (const float*)d_in[6];
    const float* av_w = (const float*)d_in[7];
    const float* w1   = (const float*)d_in[8];
    const float* b1   = (const float*)d_in[9];
    const float* w2   = (const float*)d_in[10];
    const float* b2   = (const float*)d_in[11];
    float* out = (float*)d_out;

    void *p_cat, *p_f, *p_din, *p_dout, *p_cur;
    cudaGetSymbolAddress(&p_cat,  g_cat);
    cudaGetSymbolAddress(&p_f,    g_f);
    cudaGetSymbolAddress(&p_din,  g_din);
    cudaGetSymbolAddress(&p_dout, g_dout);
    cudaGetSymbolAddress(&p_cur,  g_cursor);

    cudaMemsetAsync(p_din,  0, sizeof(int) * NN, 0);
    cudaMemsetAsync(p_dout, 0, sizeof(int) * NN, 0);
    cudaMemsetAsync(p_cur,  0, sizeof(int) * NN, 0);

    float* cat = (float*)p_cat;
    float* f   = (float*)p_f;

    const int sm128 = 2 * (128 + 128) * LDS_P * 4;   // 139264
    const int sm256 = 2 * (128 + 256) * LDS_P * 4;   // 208896
    cudaFuncSetAttribute(gemm_mma<128, false>, cudaFuncAttributeMaxDynamicSharedMemorySize, sm128);
    cudaFuncSetAttribute(gemm_mma<256, true>,  cudaFuncAttributeMaxDynamicSharedMemorySize, sm256);

    const int MB = (NN + 127) / 128;   // 391

    // h = x @ fc_w.T + fc_b  -> cat cols 0..127
    gemm_mma<128, false><<<dim3(1, MB), 256, sm128>>>(x, DIMD, fc_w, DIMD, fc_b,
                                                      cat, CATD, NN, DIMD);
    // CSR build (independent of h)
    deg_kernel<<<(EE + 255) / 256, 256>>>(src, dst);
    scan_kernel<<<1, 1024>>>();
    scatter_kernel<<<(EE + 255) / 256, 256>>>(src, dst);
    // su/sv
    suv_kernel<<<(NN * 16 + 255) / 256, 256>>>(au_w, au_b, av_w);
    // edge scores + norm (slot order)
    edge_score_kernel<<<(EE + 255) / 256, 256>>>(src, dst);
    // warp-per-dst aggregation, no atomics
    agg_kernel<<<(NN * 32 + 255) / 256, 256>>>();
    // f = gelu(cat @ w1.T + b1)
    gemm_mma<256, true><<<dim3(HIDD / 256, MB), 256, sm256>>>(cat, CATD, w1, CATD, b1,
                                                              f, HIDD, NN, CATD);
    // out = f @ w2.T + b2
    gemm_mma<128, false><<<dim3(DIMD / 128, MB), 256, sm128>>>(f, HIDD, w2, HIDD, b2,
                                                               out, DIMD, NN, HIDD);
}

// round 9
// speedup vs baseline: 2.4352x; 1.1681x over previous
#include <cuda_runtime.h>
#include <cstdint>
#include <math.h>

#define NN   50000
#define EE   800000
#define DIMD 128
#define CATD 512
#define HIDD 512

// ---------------- scratch (device globals; no allocations allowed) ----------
__device__ __align__(16) float g_cat[(size_t)NN * CATD];   // [h | msg | msg2 | msg3] (tf32-patterned)
__device__ __align__(16) float g_f[(size_t)NN * HIDD];     // gelu(...) (tf32-patterned)
__device__ __align__(16) float g_xt[(size_t)NN * DIMD];    // x pre-rounded to tf32
__device__ __align__(16) float g_fcw[DIMD * DIMD];
__device__ __align__(16) float g_w1t[HIDD * CATD];
__device__ __align__(16) float g_w2t[DIMD * HIDD];
__device__ __align__(16) float g_suv[NN * 16];             // su[0..7], sv[8..15]
__device__ __align__(16) float g_ex[(size_t)EE * 8];       // exp scores, SLOT order
__device__ float g_norm[EE];                               // sym-norm, SLOT order
__device__ int   g_din[NN];
__device__ int   g_dout[NN];
__device__ int   g_rowstart[NN + 1];
__device__ int   g_cursor[NN];
__device__ int   g_ssrc[EE];     // src node per slot

__device__ __forceinline__ float rtf32(float x) {
    uint32_t r;
    asm("cvt.rna.tf32.f32 %0, %1;" : "=r"(r) : "f"(x));
    return __uint_as_float(r);
}

__device__ __forceinline__ void cpa16(uint32_t dst, const void* src, int pbytes) {
    asm volatile("cp.async.cg.shared.global [%0], [%1], 16, %2;"
                 :: "r"(dst), "l"(src), "r"(pbytes));
}
__device__ __forceinline__ void cpa_commit() {
    asm volatile("cp.async.commit_group;");
}
template <int NG>
__device__ __forceinline__ void cpa_wait() {
    asm volatile("cp.async.wait_group %0;" :: "n"(NG));
}

// ---------------- tf32 mma.sync GEMM: C = A[M,K] @ B[N,K]^T + bias ----------
// CTA tile 128(M) x NT(N), K-chunk 32, 4-stage cp.async pipeline, 1 sync/chunk.
// Inputs must already be tf32-patterned fp32 (no cvt in mainloop).
#define KCH   32
#define LDS_P 36
#define NSTG  4

template <int NT, bool GELU, bool OUT_TF32>
__global__ __launch_bounds__(256, 1) void gemm_mma(
    const float* __restrict__ A, int lda,
    const float* __restrict__ B, int ldb,
    const float* __restrict__ bias,
    float* __restrict__ C, int ldc,
    int M, int K)
{
    constexpr int ASZ = 128 * LDS_P;         // floats per stage
    constexpr int BSZ = NT  * LDS_P;
    constexpr int NJ2 = NT / 32;             // b-frag count (4 or 8)
    extern __shared__ float smf[];

    const int tid  = threadIdx.x;
    const int wid  = tid >> 5, lane = tid & 31;
    const int g    = lane >> 2;
    const int tg   = lane & 3;
    const int m0   = blockIdx.y * 128;
    const int n0   = blockIdx.x * NT;
    const int mw   = (wid >> 2) * 64;
    const int nw   = (wid & 3) * (NT / 4);

    float c[4][NJ2][4];
#pragma unroll
    for (int i = 0; i < 4; i++)
#pragma unroll
        for (int j = 0; j < NJ2; j++)
#pragma unroll
            for (int q = 0; q < 4; q++) c[i][j][q] = 0.f;

    const int KC = K / KCH;

    auto stage = [&](int cc) {
        if (cc < KC) {
            const int kc = cc * KCH;
            float* sA = smf + (cc % NSTG) * (ASZ + BSZ);
            float* sB = sA + ASZ;
            uint32_t sAu = (uint32_t)__cvta_generic_to_shared(sA);
            uint32_t sBu = (uint32_t)__cvta_generic_to_shared(sB);
#pragma unroll
            for (int it = 0; it < 4; it++) {           // 128 rows x 8 float4
                int q   = tid + it * 256;
                int row = q >> 3;
                int kq  = (q & 7) << 2;
                int m   = m0 + row;
                int ok  = (m < M) ? 16 : 0;
                const float* srcp = &A[(size_t)(ok ? m : 0) * lda + kc + kq];
                cpa16(sAu + (row * LDS_P + kq) * 4, srcp, ok);
            }
#pragma unroll
            for (int it = 0; it < NT / 32; it++) {     // NT rows x 8 float4
                int q   = tid + it * 256;
                int row = q >> 3;
                int kq  = (q & 7) << 2;
                cpa16(sBu + (row * LDS_P + kq) * 4,
                      &B[(size_t)(n0 + row) * ldb + kc + kq], 16);
            }
        }
        cpa_commit();
    };

#pragma unroll
    for (int s = 0; s < NSTG - 1; s++) stage(s);

    for (int cch = 0; cch < KC; cch++) {
        cpa_wait<NSTG - 2>();
        __syncthreads();

        const float* sA = smf + (cch % NSTG) * (ASZ + BSZ);
        const float* sB = sA + ASZ;
        const uint32_t* uA = (const uint32_t*)sA;
        const uint32_t* uB = (const uint32_t*)sB;
#pragma unroll
        for (int ks = 0; ks < KCH / 8; ks++) {
            uint32_t a[4][4], b[NJ2][2];
#pragma unroll
            for (int i = 0; i < 4; i++) {
                int r  = (mw + i * 16 + g) * LDS_P + ks * 8 + tg;
                a[i][0] = uA[r];
                a[i][1] = uA[r + 8 * LDS_P];
                a[i][2] = uA[r + 4];
                a[i][3] = uA[r + 8 * LDS_P + 4];
            }
#pragma unroll
            for (int j = 0; j < NJ2; j++) {
                int r = (nw + j * 8 + g) * LDS_P + ks * 8 + tg;
                b[j][0] = uB[r];
                b[j][1] = uB[r + 4];
            }
#pragma unroll
            for (int i = 0; i < 4; i++)
#pragma unroll
                for (int j = 0; j < NJ2; j++) {
                    asm volatile(
                        "mma.sync.aligned.m16n8k8.row.col.f32.tf32.tf32.f32 "
                        "{%0,%1,%2,%3}, {%4,%5,%6,%7}, {%8,%9}, {%0,%1,%2,%3};"
                        : "+f"(c[i][j][0]), "+f"(c[i][j][1]),
                          "+f"(c[i][j][2]), "+f"(c[i][j][3])
                        : "r"(a[i][0]), "r"(a[i][1]), "r"(a[i][2]), "r"(a[i][3]),
                          "r"(b[j][0]), "r"(b[j][1]));
                }
        }
        stage(cch + NSTG - 1);
    }

    // ---- epilogue: bias (+GELU) (+tf32 round), store ----
#pragma unroll
    for (int i = 0; i < 4; i++) {
        int r0 = m0 + mw + i * 16 + g;
        int r1 = r0 + 8;
#pragma unroll
        for (int j = 0; j < NJ2; j++) {
            int n = n0 + nw + j * 8 + tg * 2;
            float bx = bias[n], by = bias[n + 1];
            float v0 = c[i][j][0] + bx, v1 = c[i][j][1] + by;
            float v2 = c[i][j][2] + bx, v3 = c[i][j][3] + by;
            if (GELU) {
                v0 = 0.5f * v0 * (1.f + erff(v0 * 0.70710678118654752f));
                v1 = 0.5f * v1 * (1.f + erff(v1 * 0.70710678118654752f));
                v2 = 0.5f * v2 * (1.f + erff(v2 * 0.70710678118654752f));
                v3 = 0.5f * v3 * (1.f + erff(v3 * 0.70710678118654752f));
            }
            if (OUT_TF32) {
                v0 = rtf32(v0); v1 = rtf32(v1); v2 = rtf32(v2); v3 = rtf32(v3);
            }
            if (r0 < M) {
                C[(size_t)r0 * ldc + n]     = v0;
                C[(size_t)r0 * ldc + n + 1] = v1;
            }
            if (r1 < M) {
                C[(size_t)r1 * ldc + n]     = v2;
                C[(size_t)r1 * ldc + n + 1] = v3;
            }
        }
    }
}

// ---------------- tf32 pre-round converters ---------------------------------
__global__ void cvt_kernel(const float* __restrict__ in, float* __restrict__ out,
                           int n4)
{
    int i = blockIdx.x * blockDim.x + threadIdx.x;
    if (i >= n4) return;
    float4 v = *(const float4*)&in[i * 4];
    v.x = rtf32(v.x); v.y = rtf32(v.y); v.z = rtf32(v.z); v.w = rtf32(v.w);
    *(float4*)&out[i * 4] = v;
}

// ---------------- su/sv ----------------------------------------------------
__global__ void suv_kernel(const float* __restrict__ au_w,
                           const float* __restrict__ au_b,
                           const float* __restrict__ av_w)
{
    int idx = blockIdx.x * blockDim.x + threadIdx.x;
    if (idx >= NN * 16) return;
    int n = idx >> 4;
    int j = idx & 15;
    const float* w = (j < 8) ? &au_w[j * DIMD] : &av_w[(j - 8) * DIMD];
    const float* hrow = &g_cat[(size_t)n * CATD];
    float s = 0.f;
#pragma unroll
    for (int i = 0; i < DIMD; i += 4) {
        float4 hv = *(const float4*)&hrow[i];
        float4 wv = *(const float4*)&w[i];
        s += hv.x * wv.x + hv.y * wv.y + hv.z * wv.z + hv.w * wv.w;
    }
    if (j < 8) s += au_b[j];
    g_suv[idx] = s;
}

// ---------------- CSR build: degree histogram -------------------------------
__global__ void deg_kernel(const int* __restrict__ src,
                           const int* __restrict__ dst)
{
    int e = blockIdx.x * blockDim.x + threadIdx.x;
    if (e >= EE) return;
    atomicAdd(&g_din[dst[e]], 1);
    atomicAdd(&g_dout[src[e]], 1);
}

// ---------------- exclusive scan of g_din -> g_rowstart (single block) ------
__global__ __launch_bounds__(1024, 1) void scan_kernel()
{
    __shared__ int part[1024];
    const int t = threadIdx.x;
    const int PER = (NN + 1023) / 1024;   // 49
    const int base = t * PER;
    int s = 0;
    for (int i = 0; i < PER; i++) {
        int n = base + i;
        if (n < NN) s += g_din[n];
    }
    part[t] = s;
    __syncthreads();
    for (int off = 1; off < 1024; off <<= 1) {
        int v = (t >= off) ? part[t - off] : 0;
        __syncthreads();
        part[t] += v;
        __syncthreads();
    }
    int run = (t == 0) ? 0 : part[t - 1];
    for (int i = 0; i < PER; i++) {
        int n = base + i;
        if (n < NN) {
            g_rowstart[n] = run;
            run += g_din[n];
        }
    }
    if (t == 1023) g_rowstart[NN] = run;
}

// ---------------- fused scatter + edge score --------------------------------
__global__ void scatter_score_kernel(const int* __restrict__ src,
                                     const int* __restrict__ dst)
{
    int e = blockIdx.x * blockDim.x + threadIdx.x;
    if (e >= EE) return;
    int s = src[e], d = dst[e];
    int pos  = atomicAdd(&g_cursor[d], 1);
    int slot = g_rowstart[d] + pos;
    g_ssrc[slot] = s;

    const float* su = &g_suv[s * 16];
    const float* sv = &g_suv[d * 16 + 8];
    float ex[8];
#pragma unroll
    for (int k = 0; k < 8; k++) {
        float v = su[k] + sv[k];
        v = (v > 0.f) ? v : 0.2f * v;     // LeakyReLU(0.2)
        ex[k] = __expf(v);                // softmax shift-invariant: skip max
    }
    *(float4*)&g_ex[(size_t)slot * 8 + 0] = make_float4(ex[0], ex[1], ex[2], ex[3]);
    *(float4*)&g_ex[(size_t)slot * 8 + 4] = make_float4(ex[4], ex[5], ex[6], ex[7]);
    g_norm[slot] = rsqrtf((float)g_dout[s] * (float)g_dout[d]);
}

// ---------------- warp-per-dst fused aggregation (no atomics) ---------------
__global__ __launch_bounds__(256) void agg_kernel()
{
    int gw   = (blockIdx.x * blockDim.x + threadIdx.x) >> 5;
    int lane = threadIdx.x & 31;
    if (gw >= NN) return;
    const int d  = gw;
    const int r0 = g_rowstart[d];
    const int r1 = g_rowstart[d + 1];
    const int deg = r1 - r0;

    // pass 1: softmax denominators (8 heads)
    float den[8] = {0.f, 0.f, 0.f, 0.f, 0.f, 0.f, 0.f, 0.f};
    for (int i = r0 + lane; i < r1; i += 32) {
        float4 a = *(const float4*)&g_ex[(size_t)i * 8];
        float4 b = *(const float4*)&g_ex[(size_t)i * 8 + 4];
        den[0] += a.x; den[1] += a.y; den[2] += a.z; den[3] += a.w;
        den[4] += b.x; den[5] += b.y; den[6] += b.z; den[7] += b.w;
    }
#pragma unroll
    for (int k = 0; k < 8; k++)
#pragma unroll
        for (int off = 16; off; off >>= 1)
            den[k] += __shfl_xor_sync(0xFFFFFFFFu, den[k], off);

    const int d0 = lane * 4;
    const int kb = d0 & 7;
    float4 invden;
    invden.x = 1.f / den[kb + 0];
    invden.y = 1.f / den[kb + 1];
    invden.z = 1.f / den[kb + 2];
    invden.w = 1.f / den[kb + 3];

    // pass 2: accumulate msg / sum / msg3 in registers
    float4 am = make_float4(0.f, 0.f, 0.f, 0.f);
    float4 as = make_float4(0.f, 0.f, 0.f, 0.f);
    float4 a3 = make_float4(0.f, 0.f, 0.f, 0.f);
#pragma unroll 2
    for (int i = r0; i < r1; i++) {
        int   s   = g_ssrc[i];
        float nrm = g_norm[i];
        float4 ex = *(const float4*)&g_ex[(size_t)i * 8 + kb];
        float4 h  = *(const float4*)&g_cat[(size_t)s * CATD + d0];
        am.x += h.x * ex.x * invden.x;
        am.y += h.y * ex.y * invden.y;
        am.z += h.z * ex.z * invden.z;
        am.w += h.w * ex.w * invden.w;
        as.x += h.x; as.y += h.y; as.z += h.z; as.w += h.w;
        a3.x += h.x * nrm; a3.y += h.y * nrm;
        a3.z += h.z * nrm; a3.w += h.w * nrm;
    }

    float invd = 1.f / fmaxf((float)deg, 1.f);
    float* base = &g_cat[(size_t)d * CATD];
    *(float4*)(base + 128 + d0) = make_float4(rtf32(am.x), rtf32(am.y),
                                              rtf32(am.z), rtf32(am.w));
    *(float4*)(base + 256 + d0) = make_float4(rtf32(as.x * invd), rtf32(as.y * invd),
                                              rtf32(as.z * invd), rtf32(as.w * invd));
    *(float4*)(base + 384 + d0) = make_float4(rtf32(a3.x), rtf32(a3.y),
                                              rtf32(a3.z), rtf32(a3.w));
}

// ---------------------------------------------------------------------------
extern "C" void kernel_launch(void* const* d_in, const int* in_sizes, int n_in,
                              void* d_out, int out_size)
{
    const float* x    = (const float*)d_in[0];
    const int*   src  = (const int*)d_in[1];
    const int*   dst  = (const int*)d_in[2];
    const float* fc_w = (const float*)d_in[3];
    const float* fc_b = (const float*)d_in[4];
    const float* au_w = (const float*)d_in[5];
    const float* au_b = (const float*)d_in[6];
    const float* av_w = (const float*)d_in[7];
    const float* w1   = (const float*)d_in[8];
    const float* b1   = (const float*)d_in[9];
    const float* w2   = (const float*)d_in[10];
    const float* b2   = (const float*)d_in[11];
    float* out = (float*)d_out;

    void *p_cat, *p_f, *p_xt, *p_fcw, *p_w1t, *p_w2t, *p_din, *p_dout, *p_cur;
    cudaGetSymbolAddress(&p_cat,  g_cat);
    cudaGetSymbolAddress(&p_f,    g_f);
    cudaGetSymbolAddress(&p_xt,   g_xt);
    cudaGetSymbolAddress(&p_fcw,  g_fcw);
    cudaGetSymbolAddress(&p_w1t,  g_w1t);
    cudaGetSymbolAddress(&p_w2t,  g_w2t);
    cudaGetSymbolAddress(&p_din,  g_din);
    cudaGetSymbolAddress(&p_dout, g_dout);
    cudaGetSymbolAddress(&p_cur,  g_cursor);

    cudaMemsetAsync(p_din,  0, sizeof(int) * NN, 0);
    cudaMemsetAsync(p_dout, 0, sizeof(int) * NN, 0);
    cudaMemsetAsync(p_cur,  0, sizeof(int) * NN, 0);

    float* cat = (float*)p_cat;
    float* f   = (float*)p_f;
    float* xt  = (float*)p_xt;
    float* fcw = (float*)p_fcw;
    float* w1t = (float*)p_w1t;
    float* w2t = (float*)p_w2t;

    const int sm128 = NSTG * (128 + 128) * LDS_P * 4;   // 147456
    const int sm256 = NSTG * (128 + 256) * LDS_P * 4;   // 221184
    cudaFuncSetAttribute(gemm_mma<128, false, true>,
                         cudaFuncAttributeMaxDynamicSharedMemorySize, sm128);
    cudaFuncSetAttribute(gemm_mma<128, false, false>,
                         cudaFuncAttributeMaxDynamicSharedMemorySize, sm128);
    cudaFuncSetAttribute(gemm_mma<256, true, true>,
                         cudaFuncAttributeMaxDynamicSharedMemorySize, sm256);

    const int MB = (NN + 127) / 128;   // 391

    // pre-round tf32 inputs
    cvt_kernel<<<(NN * DIMD / 4 + 255) / 256, 256>>>(x, xt, NN * DIMD / 4);
    cvt_kernel<<<(DIMD * DIMD / 4 + 255) / 256, 256>>>(fc_w, fcw, DIMD * DIMD / 4);
    cvt_kernel<<<(HIDD * CATD / 4 + 255) / 256, 256>>>(w1, w1t, HIDD * CATD / 4);
    cvt_kernel<<<(DIMD * HIDD / 4 + 255) / 256, 256>>>(w2, w2t, DIMD * HIDD / 4);

    // CSR build (independent of h)
    deg_kernel<<<(EE + 255) / 256, 256>>>(src, dst);
    scan_kernel<<<1, 1024>>>();

    // h = x @ fc_w.T + fc_b  -> cat cols 0..127 (tf32-rounded)
    gemm_mma<128, false, true><<<dim3(1, MB), 256, sm128>>>(
        xt, DIMD, fcw, DIMD, fc_b, cat, CATD, NN, DIMD);
    // su/sv
    suv_kernel<<<(NN * 16 + 255) / 256, 256>>>(au_w, au_b, av_w);
    // fused scatter + edge scores + norm (slot order)
    scatter_score_kernel<<<(EE + 255) / 256, 256>>>(src, dst);
    // warp-per-dst aggregation, no atomics
    agg_kernel<<<(NN * 32 + 255) / 256, 256>>>();
    // f = gelu(cat @ w1.T + b1) (tf32-rounded)
    gemm_mma<256, true, true><<<dim3(HIDD / 256, MB), 256, sm256>>>(
        cat, CATD, w1t, CATD, b1, f, HIDD, NN, CATD);
    // out = f @ w2.T + b2 (full fp32 out)
    gemm_mma<128, false, false><<<dim3(DIMD / 128, MB), 256, sm128>>>(
        f, HIDD, w2t, HIDD, b2, out, DIMD, NN, HIDD);
}

// round 10
// speedup vs baseline: 3.6623x; 1.5039x over previous
#include <cuda_runtime.h>
#include <cuda_fp16.h>
#include <cstdint>
#include <math.h>

#define NN   50000
#define EE   800000
#define DIMD 128
#define CATD 512
#define HIDD 512

// ---------------- scratch (device globals; no allocations allowed) ----------
__device__ __align__(16) float  g_h[(size_t)NN * DIMD];     // h fp32 (half-rounded)
__device__ __align__(16) __half g_cath[(size_t)NN * CATD];  // [h|msg|msg2|msg3] half
__device__ __align__(16) __half g_fh[(size_t)NN * HIDD];    // gelu(...) half
__device__ __align__(16) __half g_xh[(size_t)NN * DIMD];
__device__ __align__(16) __half g_fcwh[DIMD * DIMD];
__device__ __align__(16) __half g_w1h[HIDD * CATD];
__device__ __align__(16) __half g_w2h[DIMD * HIDD];
__device__ __align__(16) float  g_suv[NN * 16];             // su[0..7], sv[8..15]
__device__ __align__(16) float  g_ex[(size_t)EE * 8];       // exp scores, SLOT order
__device__ float g_norm[EE];
__device__ int   g_din[NN];
__device__ int   g_dout[NN];
__device__ int   g_rowstart[NN + 1];
__device__ int   g_cursor[NN];
__device__ int   g_ssrc[EE];

__device__ __forceinline__ float rhalf(float x) {
    return __half2float(__float2half_rn(x));
}

__device__ __forceinline__ void cpa16(uint32_t dst, const void* src, int pbytes) {
    asm volatile("cp.async.cg.shared.global [%0], [%1], 16, %2;"
                 :: "r"(dst), "l"(src), "r"(pbytes));
}
__device__ __forceinline__ void cpa_commit() {
    asm volatile("cp.async.commit_group;");
}
template <int NG>
__device__ __forceinline__ void cpa_wait() {
    asm volatile("cp.async.wait_group %0;" :: "n"(NG));
}

// ---------------- fp16 mma.sync GEMM: C = A[M,K] @ B[N,K]^T + bias ----------
// CTA 128(M) x NT(N), K-chunk 64 halves, 4-stage cp.async pipeline, 1 sync/chunk.
#define KCH   64
#define LDS_P 72      // halves per row (64 + 8 pad); conflict-free frag LDS
#define NSTG  4

template <int NT, bool GELU, bool F32OUT, bool HOUT, bool RND>
__global__ __launch_bounds__(256, 1) void gemm_h(
    const __half* __restrict__ A, int lda,
    const __half* __restrict__ B, int ldb,
    const float* __restrict__ bias,
    float* __restrict__ Cf, int ldcf,
    __half* __restrict__ Ch, int ldch,
    int M, int K)
{
    constexpr int ASZ = 128 * LDS_P;         // halves per stage
    constexpr int BSZ = NT  * LDS_P;
    constexpr int NJ2 = NT / 32;             // b-frag count (4 or 8)
    extern __shared__ __half smh[];

    const int tid  = threadIdx.x;
    const int wid  = tid >> 5, lane = tid & 31;
    const int g    = lane >> 2;
    const int tg   = lane & 3;
    const int m0   = blockIdx.y * 128;
    const int n0   = blockIdx.x * NT;
    const int mw   = (wid >> 2) * 64;
    const int nw   = (wid & 3) * (NT / 4);

    float c[4][NJ2][4];
#pragma unroll
    for (int i = 0; i < 4; i++)
#pragma unroll
        for (int j = 0; j < NJ2; j++)
#pragma unroll
            for (int q = 0; q < 4; q++) c[i][j][q] = 0.f;

    const int KC = K / KCH;

    auto stage = [&](int cc) {
        if (cc < KC) {
            const int kc = cc * KCH;
            __half* sA = smh + (cc % NSTG) * (ASZ + BSZ);
            __half* sB = sA + ASZ;
            uint32_t sAu = (uint32_t)__cvta_generic_to_shared(sA);
            uint32_t sBu = (uint32_t)__cvta_generic_to_shared(sB);
#pragma unroll
            for (int it = 0; it < 4; it++) {           // 128 rows x 8x16B
                int q   = tid + it * 256;
                int row = q >> 3;
                int kq  = (q & 7) << 3;                // half offset
                int m   = m0 + row;
                int ok  = (m < M) ? 16 : 0;
                const __half* srcp = &A[(size_t)(ok ? m : 0) * lda + kc + kq];
                cpa16(sAu + (row * LDS_P + kq) * 2, srcp, ok);
            }
#pragma unroll
            for (int it = 0; it < NT / 32; it++) {     // NT rows x 8x16B
                int q   = tid + it * 256;
                int row = q >> 3;
                int kq  = (q & 7) << 3;
                cpa16(sBu + (row * LDS_P + kq) * 2,
                      &B[(size_t)(n0 + row) * ldb + kc + kq], 16);
            }
        }
        cpa_commit();
    };

#pragma unroll
    for (int s = 0; s < NSTG - 1; s++) stage(s);

    for (int cch = 0; cch < KC; cch++) {
        cpa_wait<NSTG - 2>();
        __syncthreads();

        const __half* sA = smh + (cch % NSTG) * (ASZ + BSZ);
        const __half* sB = sA + ASZ;
        const uint32_t* uA = (const uint32_t*)sA;      // 2 halves per u32
        const uint32_t* uB = (const uint32_t*)sB;
#pragma unroll
        for (int ks = 0; ks < KCH / 16; ks++) {        // 4 k16 steps
            uint32_t a[4][4], b[NJ2][2];
#pragma unroll
            for (int i = 0; i < 4; i++) {
                int r  = (mw + i * 16 + g) * (LDS_P / 2) + ks * 8 + tg;
                a[i][0] = uA[r];
                a[i][1] = uA[r + 8 * (LDS_P / 2)];
                a[i][2] = uA[r + 4];
                a[i][3] = uA[r + 8 * (LDS_P / 2) + 4];
            }
#pragma unroll
            for (int j = 0; j < NJ2; j++) {
                int r = (nw + j * 8 + g) * (LDS_P / 2) + ks * 8 + tg;
                b[j][0] = uB[r];
                b[j][1] = uB[r + 4];
            }
#pragma unroll
            for (int i = 0; i < 4; i++)
#pragma unroll
                for (int j = 0; j < NJ2; j++) {
                    asm volatile(
                        "mma.sync.aligned.m16n8k16.row.col.f32.f16.f16.f32 "
                        "{%0,%1,%2,%3}, {%4,%5,%6,%7}, {%8,%9}, {%0,%1,%2,%3};"
                        : "+f"(c[i][j][0]), "+f"(c[i][j][1]),
                          "+f"(c[i][j][2]), "+f"(c[i][j][3])
                        : "r"(a[i][0]), "r"(a[i][1]), "r"(a[i][2]), "r"(a[i][3]),
                          "r"(b[j][0]), "r"(b[j][1]));
                }
        }
        stage(cch + NSTG - 1);
    }

    // ---- epilogue ----
#pragma unroll
    for (int i = 0; i < 4; i++) {
        int r0 = m0 + mw + i * 16 + g;
        int r1 = r0 + 8;
#pragma unroll
        for (int j = 0; j < NJ2; j++) {
            int n = n0 + nw + j * 8 + tg * 2;
            float bx = bias[n], by = bias[n + 1];
            float v0 = c[i][j][0] + bx, v1 = c[i][j][1] + by;
            float v2 = c[i][j][2] + bx, v3 = c[i][j][3] + by;
            if (GELU) {
                v0 = 0.5f * v0 * (1.f + erff(v0 * 0.70710678118654752f));
                v1 = 0.5f * v1 * (1.f + erff(v1 * 0.70710678118654752f));
                v2 = 0.5f * v2 * (1.f + erff(v2 * 0.70710678118654752f));
                v3 = 0.5f * v3 * (1.f + erff(v3 * 0.70710678118654752f));
            }
            if (r0 < M) {
                if (HOUT)
                    *(__half2*)&Ch[(size_t)r0 * ldch + n] = __floats2half2_rn(v0, v1);
                if (F32OUT) {
                    Cf[(size_t)r0 * ldcf + n]     = RND ? rhalf(v0) : v0;
                    Cf[(size_t)r0 * ldcf + n + 1] = RND ? rhalf(v1) : v1;
                }
            }
            if (r1 < M) {
                if (HOUT)
                    *(__half2*)&Ch[(size_t)r1 * ldch + n] = __floats2half2_rn(v2, v3);
                if (F32OUT) {
                    Cf[(size_t)r1 * ldcf + n]     = RND ? rhalf(v2) : v2;
                    Cf[(size_t)r1 * ldcf + n + 1] = RND ? rhalf(v3) : v3;
                }
            }
        }
    }
}

// ---------------- fp32 -> fp16 converter ------------------------------------
__global__ void cvth_kernel(const float* __restrict__ in, __half* __restrict__ out,
                            int n4)
{
    int i = blockIdx.x * blockDim.x + threadIdx.x;
    if (i >= n4) return;
    float4 v = *(const float4*)&in[i * 4];
    *(__half2*)&out[i * 4 + 0] = __floats2half2_rn(v.x, v.y);
    *(__half2*)&out[i * 4 + 2] = __floats2half2_rn(v.z, v.w);
}

// ---------------- su/sv: smem-staged, block = 16 nodes x 16 outputs ---------
__global__ __launch_bounds__(256) void suv_kernel(const float* __restrict__ au_w,
                                                  const float* __restrict__ au_b,
                                                  const float* __restrict__ av_w)
{
    __shared__ float sw[16][132];
    __shared__ float sh[16][132];
    const int t  = threadIdx.x;
    const int n0 = blockIdx.x * 16;

    // stage 16 weight rows (au 0..7, av 8..15)
#pragma unroll
    for (int it = 0; it < 2; it++) {
        int q   = t + it * 256;        // 0..511
        int row = q >> 5;
        int i4  = (q & 31) << 2;
        const float* wsrc = (row < 8) ? &au_w[row * DIMD] : &av_w[(row - 8) * DIMD];
        *(float4*)&sw[row][i4] = *(const float4*)&wsrc[i4];
    }
    // stage 16 h rows
#pragma unroll
    for (int it = 0; it < 2; it++) {
        int q   = t + it * 256;
        int row = q >> 5;
        int i4  = (q & 31) << 2;
        *(float4*)&sh[row][i4] = *(const float4*)&g_h[(size_t)(n0 + row) * DIMD + i4];
    }
    __syncthreads();

    const int nl = t >> 4;
    const int j  = t & 15;
    float s = 0.f;
#pragma unroll
    for (int i = 0; i < DIMD; i += 4) {
        float4 hv = *(const float4*)&sh[nl][i];
        float4 wv = *(const float4*)&sw[j][i];
        s += hv.x * wv.x + hv.y * wv.y + hv.z * wv.z + hv.w * wv.w;
    }
    if (j < 8) s += au_b[j];
    g_suv[(n0 + nl) * 16 + j] = s;
}

// ---------------- CSR build: degree histogram -------------------------------
__global__ void deg_kernel(const int* __restrict__ src,
                           const int* __restrict__ dst)
{
    int e = blockIdx.x * blockDim.x + threadIdx.x;
    if (e >= EE) return;
    atomicAdd(&g_din[dst[e]], 1);
    atomicAdd(&g_dout[src[e]], 1);
}

// ---------------- exclusive scan of g_din -> g_rowstart (single block) ------
__global__ __launch_bounds__(1024, 1) void scan_kernel()
{
    __shared__ int part[1024];
    const int t = threadIdx.x;
    const int PER = (NN + 1023) / 1024;   // 49
    const int base = t * PER;
    int s = 0;
    for (int i = 0; i < PER; i++) {
        int n = base + i;
        if (n < NN) s += g_din[n];
    }
    part[t] = s;
    __syncthreads();
    for (int off = 1; off < 1024; off <<= 1) {
        int v = (t >= off) ? part[t - off] : 0;
        __syncthreads();
        part[t] += v;
        __syncthreads();
    }
    int run = (t == 0) ? 0 : part[t - 1];
    for (int i = 0; i < PER; i++) {
        int n = base + i;
        if (n < NN) {
            g_rowstart[n] = run;
            run += g_din[n];
        }
    }
    if (t == 1023) g_rowstart[NN] = run;
}

// ---------------- fused scatter + edge score --------------------------------
__global__ void scatter_score_kernel(const int* __restrict__ src,
                                     const int* __restrict__ dst)
{
    int e = blockIdx.x * blockDim.x + threadIdx.x;
    if (e >= EE) return;
    int s = src[e], d = dst[e];
    int pos  = atomicAdd(&g_cursor[d], 1);
    int slot = g_rowstart[d] + pos;
    g_ssrc[slot] = s;

    const float* su = &g_suv[s * 16];
    const float* sv = &g_suv[d * 16 + 8];
    float ex[8];
#pragma unroll
    for (int k = 0; k < 8; k++) {
        float v = su[k] + sv[k];
        v = (v > 0.f) ? v : 0.2f * v;     // LeakyReLU(0.2)
        ex[k] = __expf(v);                // softmax shift-invariant: skip max
    }
    *(float4*)&g_ex[(size_t)slot * 8 + 0] = make_float4(ex[0], ex[1], ex[2], ex[3]);
    *(float4*)&g_ex[(size_t)slot * 8 + 4] = make_float4(ex[4], ex[5], ex[6], ex[7]);
    g_norm[slot] = rsqrtf((float)g_dout[s] * (float)g_dout[d]);
}

// ---------------- warp-per-dst fused aggregation (no atomics) ---------------
// Writes msg/msg2/msg3 directly as fp16 into g_cath cols 128..511.
__global__ __launch_bounds__(256) void agg_kernel()
{
    int gw   = (blockIdx.x * blockDim.x + threadIdx.x) >> 5;
    int lane = threadIdx.x & 31;
    if (gw >= NN) return;
    const int d  = gw;
    const int r0 = g_rowstart[d];
    const int r1 = g_rowstart[d + 1];
    const int deg = r1 - r0;

    float den[8] = {0.f, 0.f, 0.f, 0.f, 0.f, 0.f, 0.f, 0.f};
    for (int i = r0 + lane; i < r1; i += 32) {
        float4 a = *(const float4*)&g_ex[(size_t)i * 8];
        float4 b = *(const float4*)&g_ex[(size_t)i * 8 + 4];
        den[0] += a.x; den[1] += a.y; den[2] += a.z; den[3] += a.w;
        den[4] += b.x; den[5] += b.y; den[6] += b.z; den[7] += b.w;
    }
#pragma unroll
    for (int k = 0; k < 8; k++)
#pragma unroll
        for (int off = 16; off; off >>= 1)
            den[k] += __shfl_xor_sync(0xFFFFFFFFu, den[k], off);

    const int d0 = lane * 4;
    const int kb = d0 & 7;
    float4 invden;
    invden.x = 1.f / den[kb + 0];
    invden.y = 1.f / den[kb + 1];
    invden.z = 1.f / den[kb + 2];
    invden.w = 1.f / den[kb + 3];

    float4 am = make_float4(0.f, 0.f, 0.f, 0.f);
    float4 as = make_float4(0.f, 0.f, 0.f, 0.f);
    float4 a3 = make_float4(0.f, 0.f, 0.f, 0.f);
#pragma unroll 2
    for (int i = r0; i < r1; i++) {
        int   s   = g_ssrc[i];
        float nrm = g_norm[i];
        float4 ex = *(const float4*)&g_ex[(size_t)i * 8 + kb];
        float4 h  = *(const float4*)&g_h[(size_t)s * DIMD + d0];
        am.x += h.x * ex.x * invden.x;
        am.y += h.y * ex.y * invden.y;
        am.z += h.z * ex.z * invden.z;
        am.w += h.w * ex.w * invden.w;
        as.x += h.x; as.y += h.y; as.z += h.z; as.w += h.w;
        a3.x += h.x * nrm; a3.y += h.y * nrm;
        a3.z += h.z * nrm; a3.w += h.w * nrm;
    }

    float invd = 1.f / fmaxf((float)deg, 1.f);
    __half* base = &g_cath[(size_t)d * CATD];
    *(__half2*)&base[128 + d0]     = __floats2half2_rn(am.x, am.y);
    *(__half2*)&base[128 + d0 + 2] = __floats2half2_rn(am.z, am.w);
    *(__half2*)&base[256 + d0]     = __floats2half2_rn(as.x * invd, as.y * invd);
    *(__half2*)&base[256 + d0 + 2] = __floats2half2_rn(as.z * invd, as.w * invd);
    *(__half2*)&base[384 + d0]     = __floats2half2_rn(a3.x, a3.y);
    *(__half2*)&base[384 + d0 + 2] = __floats2half2_rn(a3.z, a3.w);
}

// ---------------------------------------------------------------------------
extern "C" void kernel_launch(void* const* d_in, const int* in_sizes, int n_in,
                              void* d_out, int out_size)
{
    const float* x    = (const float*)d_in[0];
    const int*   src  = (const int*)d_in[1];
    const int*   dst  = (const int*)d_in[2];
    const float* fc_w = (const float*)d_in[3];
    const float* fc_b = (const float*)d_in[4];
    const float* au_w = (const float*)d_in[5];
    const float* au_b = (const float*)d_in[6];
    const float* av_w = (const float*)d_in[7];
    const float* w1   = (const float*)d_in[8];
    const float* b1   = (const float*)d_in[9];
    const float* w2   = (const float*)d_in[10];
    const float* b2   = (const float*)d_in[11];
    float* out = (float*)d_out;

    void *p_h, *p_cath, *p_fh, *p_xh, *p_fcwh, *p_w1h, *p_w2h,
         *p_din, *p_dout, *p_cur;
    cudaGetSymbolAddress(&p_h,    g_h);
    cudaGetSymbolAddress(&p_cath, g_cath);
    cudaGetSymbolAddress(&p_fh,   g_fh);
    cudaGetSymbolAddress(&p_xh,   g_xh);
    cudaGetSymbolAddress(&p_fcwh, g_fcwh);
    cudaGetSymbolAddress(&p_w1h,  g_w1h);
    cudaGetSymbolAddress(&p_w2h,  g_w2h);
    cudaGetSymbolAddress(&p_din,  g_din);
    cudaGetSymbolAddress(&p_dout, g_dout);
    cudaGetSymbolAddress(&p_cur,  g_cursor);

    cudaMemsetAsync(p_din,  0, sizeof(int) * NN, 0);
    cudaMemsetAsync(p_dout, 0, sizeof(int) * NN, 0);
    cudaMemsetAsync(p_cur,  0, sizeof(int) * NN, 0);

    float*  hbuf = (float*)p_h;
    __half* cath = (__half*)p_cath;
    __half* fh   = (__half*)p_fh;
    __half* xh   = (__half*)p_xh;
    __half* fcwh = (__half*)p_fcwh;
    __half* w1h  = (__half*)p_w1h;
    __half* w2h  = (__half*)p_w2h;

    const int sm128 = NSTG * (128 + 128) * LDS_P * 2;   // 147456
    const int sm256 = NSTG * (128 + 256) * LDS_P * 2;   // 221184
    cudaFuncSetAttribute((const void*)gemm_h<128, false, true, true, true>,
                         cudaFuncAttributeMaxDynamicSharedMemorySize, sm128);
    cudaFuncSetAttribute((const void*)gemm_h<256, true, false, true, false>,
                         cudaFuncAttributeMaxDynamicSharedMemorySize, sm256);
    cudaFuncSetAttribute((const void*)gemm_h<128, false, true, false, false>,
                         cudaFuncAttributeMaxDynamicSharedMemorySize, sm128);

    const int MB = (NN + 127) / 128;   // 391

    // pre-convert inputs to fp16
    cvth_kernel<<<(NN * DIMD / 4 + 255) / 256, 256>>>(x, xh, NN * DIMD / 4);
    cvth_kernel<<<(DIMD * DIMD / 4 + 255) / 256, 256>>>(fc_w, fcwh, DIMD * DIMD / 4);
    cvth_kernel<<<(HIDD * CATD / 4 + 255) / 256, 256>>>(w1, w1h, HIDD * CATD / 4);
    cvth_kernel<<<(DIMD * HIDD / 4 + 255) / 256, 256>>>(w2, w2h, DIMD * HIDD / 4);

    // CSR build (independent of h)
    deg_kernel<<<(EE + 255) / 256, 256>>>(src, dst);
    scan_kernel<<<1, 1024>>>();

    // h = x @ fc_w.T + fc_b  -> g_h (fp32, half-rounded) + g_cath cols 0..127
    gemm_h<128, false, true, true, true><<<dim3(1, MB), 256, sm128>>>(
        xh, DIMD, fcwh, DIMD, fc_b, hbuf, DIMD, cath, CATD, NN, DIMD);
    // su/sv (smem-staged)
    suv_kernel<<<NN / 16, 256>>>(au_w, au_b, av_w);
    // fused scatter + edge scores + norm (slot order)
    scatter_score_kernel<<<(EE + 255) / 256, 256>>>(src, dst);
    // warp-per-dst aggregation -> g_cath cols 128..511 (fp16)
    agg_kernel<<<(NN * 32 + 255) / 256, 256>>>();
    // f = gelu(cat @ w1.T + b1) -> g_fh (fp16)
    gemm_h<256, true, false, true, false><<<dim3(HIDD / 256, MB), 256, sm256>>>(
        cath, CATD, w1h, CATD, b1, (float*)nullptr, 0, fh, HIDD, NN, CATD);
    // out = f @ w2.T + b2 (fp32)
    gemm_h<128, false, true, false, false><<<dim3(DIMD / 128, MB), 256, sm128>>>(
        fh, HIDD, w2h, HIDD, b2, out, DIMD, (__half*)nullptr, 0, NN, HIDD);
}